// round 13
// baseline (speedup 1.0000x reference)
#include <cuda_runtime.h>
#include <math.h>

#define K_TOP    6000
#define CAND_CAP 16384
#define NMS_CAP  1024
#define H16BINS  16384     // 16-bit score-prefix bins: (u>>16)-0x8000, u in [0x8000,0xBF80]
#define MSTRIDE  33        // padded mask row stride (no 32-way bank conflicts)
#define NGROUPS  16

// ---------------- scratch (device globals; no allocations) ----------------
__device__ unsigned int       g_hist16[H16BINS];
__device__ unsigned int       g_base[H16BINS];    // per-bin exact global rank base
__device__ unsigned int       g_cursor[H16BINS];  // per-bin scatter cursor
__device__ unsigned int       g_meta[8];          // [0]=t16 crossing bin
__device__ unsigned long long g_cand[CAND_CAP];   // bucketed candidates
__device__ float4             g_gbox[NGROUPS * NMS_CAP];
__device__ int                g_gpos[NGROUPS * NMS_CAP];
__device__ unsigned int       g_gcnt[NGROUPS];

// order-preserving float<->uint transform
__device__ __forceinline__ unsigned int f2u(float f) {
    unsigned int b = __float_as_uint(f);
    return b ^ ((b & 0x80000000u) ? 0xFFFFFFFFu : 0x80000000u);
}
__device__ __forceinline__ float u2f(unsigned int u) {
    unsigned int b = (u & 0x80000000u) ? (u ^ 0x80000000u) : ~u;
    return __uint_as_float(b);
}
__device__ __forceinline__ int bin16(unsigned int u) {
    int b = (int)(u >> 16) - 0x8000;
    b = (b < 0) ? 0 : b;
    return (b > H16BINS - 1) ? H16BINS - 1 : b;
}

// ---------------- kernel 1: 16-bit-prefix histogram of fg scores ----------------
__global__ void k_hist16(const float* __restrict__ probs, int n_groups) {
    extern __shared__ unsigned int sh[];           // H16BINS
    for (int k = threadIdx.x; k < H16BINS; k += blockDim.x) sh[k] = 0u;
    __syncthreads();

    const float4* __restrict__ p4 = (const float4*)probs;
    int stride = gridDim.x * blockDim.x;
    for (int g = blockIdx.x * blockDim.x + threadIdx.x; g < n_groups; g += stride) {
        float4 A = p4[g * 3 + 0], B = p4[g * 3 + 1], C = p4[g * 3 + 2];
        float s[8] = {A.y, A.z, B.x, B.y, B.w, C.x, C.z, C.w};
#pragma unroll
        for (int k = 0; k < 8; k++) {
            int bin = bin16(f2u(s[k]));
            unsigned int act = __activemask();
            unsigned int peers = __match_any_sync(act, bin);
            int leader = __ffs(peers) - 1;
            if ((threadIdx.x & 31) == leader)
                atomicAdd(&sh[bin], (unsigned int)__popc(peers));
        }
    }
    __syncthreads();
    for (int k = threadIdx.x; k < H16BINS; k += blockDim.x) {
        unsigned int v = sh[k];
        if (v) atomicAdd(&g_hist16[k], v);
    }
}

// --- kernel 2: crossing bin + per-bin rank bases (suffix sums) + cursors ---
__global__ void k_binit() {
    __shared__ unsigned int ssum[1024];
    int tid = threadIdx.x;
    const int bpt = H16BINS / 1024;    // 16
    int base = tid * bpt;
    unsigned int h[bpt];
    unsigned int cs = 0;
#pragma unroll
    for (int k = 0; k < bpt; k++) { h[k] = g_hist16[base + k]; cs += h[k]; }
    ssum[tid] = cs; __syncthreads();
    for (int off = 1; off < 1024; off <<= 1) {     // inclusive suffix sum
        unsigned int v = (tid + off < 1024) ? ssum[tid + off] : 0u;
        __syncthreads();
        ssum[tid] += v;
        __syncthreads();
    }
    unsigned int excl = (tid < 1023) ? ssum[tid + 1] : 0u;

    unsigned int run = excl;                       // suffix base per bin
#pragma unroll
    for (int k = bpt - 1; k >= 0; k--) {
        g_base[base + k] = run;
        g_cursor[base + k] = run;
        run += h[k];
    }
    if (ssum[tid] >= (unsigned)K_TOP && excl < (unsigned)K_TOP) {   // unique crossing
        unsigned int r2 = excl;
        for (int k = bpt - 1; k >= 0; k--) {
            if (r2 + h[k] >= (unsigned)K_TOP) { g_meta[0] = (unsigned int)(base + k); break; }
            r2 += h[k];
        }
    }
}

// --- kernel 3: pass 2 -- scatter candidates into their bin's segment ---
__global__ void k_scatter(const float* __restrict__ probs, int n_groups) {
    int t16 = (int)g_meta[0];
    int lane = threadIdx.x & 31;

    const float4* __restrict__ p4 = (const float4*)probs;
    int stride = gridDim.x * blockDim.x;
    for (int g = blockIdx.x * blockDim.x + threadIdx.x; g < n_groups; g += stride) {
        float4 A = p4[g * 3 + 0], B = p4[g * 3 + 1], C = p4[g * 3 + 2];
        float s[8] = {A.y, A.z, B.x, B.y, B.w, C.x, C.z, C.w};
#pragma unroll
        for (int k = 0; k < 8; k++) {
            unsigned int u = f2u(s[k]);
            int bin = bin16(u);
            bool e = (bin >= t16);
            unsigned int act = __activemask();
            unsigned int ball_e = __ballot_sync(act, e);
            if (ball_e) {
                unsigned int peers = __match_any_sync(act, bin) & ball_e;
                if (e) {
                    int leader = __ffs(peers) - 1;
                    unsigned int basep = 0;
                    if (lane == leader)
                        basep = atomicAdd(&g_cursor[bin], (unsigned int)__popc(peers));
                    basep = __shfl_sync(ball_e, basep, leader);
                    unsigned int my = basep + __popc(peers & ((1u << lane) - 1u));
                    if (my < CAND_CAP) {
                        unsigned int flat = (unsigned int)((g * 4 + (k >> 1)) * 2 + (k & 1));
                        g_cand[my] = ((unsigned long long)u << 32) |
                                     (unsigned long long)(0xFFFFFFFFu - flat);
                    }
                }
            }
        }
    }
}

// --- kernel 4: bucketed exact rank (tiny per-bin segments) + decode + scatter ---
__global__ void k_rank(const float* __restrict__ deltas,
                       const float* __restrict__ anchors,
                       float* __restrict__ out, int n_anchors) {
    int t16 = (int)g_meta[0];
    int m = (int)min(g_base[t16] + g_hist16[t16], (unsigned int)CAND_CAP);
    int lane = threadIdx.x & 31;
    int warp = blockIdx.x * (blockDim.x >> 5) + (threadIdx.x >> 5);
    int nwarps = gridDim.x * (blockDim.x >> 5);

    for (int item = warp; item < m; item += nwarps) {
        unsigned long long key = g_cand[item];
        int bin = bin16((unsigned int)(key >> 32));
        int seg0 = (int)g_base[bin];
        int segn = (int)g_hist16[bin];

        unsigned int cnt = 0u;
        for (int j = seg0 + lane; j < seg0 + segn; j += 32)
            cnt += (g_cand[j] > key) ? 1u : 0u;
#pragma unroll
        for (int off = 16; off > 0; off >>= 1)
            cnt += __shfl_down_sync(0xFFFFFFFFu, cnt, off);

        if (lane == 0) {
            int rk = seg0 + (int)cnt;
            if (rk < K_TOP) {
                unsigned int u = (unsigned int)(key >> 32);
                unsigned int flat = 0xFFFFFFFFu - (unsigned int)(key & 0xFFFFFFFFu);
                int prop = (int)(flat >> 1);
                int cls = (int)(flat & 1u) + 1;
                float score = u2f(u);
                int b = prop / n_anchors;
                int ai = prop - b * n_anchors;

                const float* a  = anchors + (size_t)ai * 4;
                const float* dl = deltas + (size_t)prop * 4;
                float d0 = dl[0] * 0.1f, d1 = dl[1] * 0.1f;
                float d2 = dl[2] * 0.2f, d3 = dl[3] * 0.2f;

                const float inv = 1.0f / 512.0f;
                float ay1 = a[0] * inv, ax1 = a[1] * inv;
                float ay2 = a[2] * inv, ax2 = a[3] * inv;
                float h  = ay2 - ay1;
                float w2 = ax2 - ax1;
                float cy = ay1 + 0.5f * h + d0 * h;
                float cx = ax1 + 0.5f * w2 + d1 * w2;
                h  = h * expf(d2);
                w2 = w2 * expf(d3);
                float y1 = cy - 0.5f * h;
                float x1 = cx - 0.5f * w2;
                float y2 = y1 + h;
                float x2 = x1 + w2;
                y1 = fminf(fmaxf(y1 * 512.0f, 0.0f), 512.0f);
                x1 = fminf(fmaxf(x1 * 512.0f, 0.0f), 512.0f);
                y2 = fminf(fmaxf(y2 * 512.0f, 0.0f), 512.0f);
                x2 = fminf(fmaxf(x2 * 512.0f, 0.0f), 512.0f);

                out[rk * 6 + 0] = y1;
                out[rk * 6 + 1] = x1;
                out[rk * 6 + 2] = y2;
                out[rk * 6 + 3] = x2;
                out[rk * 6 + 4] = score;
                out[rk * 6 + 5] = 1.0f;                 // keep (finalized by NMS)
                out[K_TOP * 6 + rk] = (float)cls;       // class_ids
                out[K_TOP * 7 + rk] = (float)b;         // batch ids

                int grp = b * 2 + (int)(flat & 1u);
                unsigned int slot = atomicAdd(&g_gcnt[grp], 1u);   // arbitrary order
                if (slot < NMS_CAP) {
                    g_gbox[grp * NMS_CAP + slot] = make_float4(y1, x1, y2, x2);
                    g_gpos[grp * NMS_CAP + slot] = rk;
                }
            }
        }
    }
}

// ------- kernel 5: per-group NMS (sorts by global rank first) + cleanup -------
__global__ void k_nms(float* __restrict__ out) {
    extern __shared__ unsigned char dyn[];
    float* sy1   = (float*)dyn;
    float* sx1   = sy1 + NMS_CAP;
    float* sy2   = sx1 + NMS_CAP;
    float* sx2   = sy2 + NMS_CAP;
    float* sarea = sx2 + NMS_CAP;
    int* spos    = (int*)(sarea + NMS_CAP);
    unsigned int* mask = (unsigned int*)(spos + NMS_CAP);   // [NMS_CAP][MSTRIDE]
    int* rkraw = (int*)mask;                                // pre-mask scratch

    __shared__ unsigned int s_remv[32];

    int tid = threadIdx.x;
    int grp = blockIdx.x;

    // cleanup scratch for next replay: 16 blocks x 1024 threads = 16384 bins
    g_hist16[grp * 1024 + tid] = 0u;
    // (g_base/g_cursor/g_meta rewritten by k_binit each replay)

    int n = min((int)g_gcnt[grp], NMS_CAP);

    // load raw (unordered) entries; sort by global rank via rank-by-count
    float4 bx = make_float4(0.f, 0.f, 0.f, 0.f);
    int ps = 0;
    if (tid < n) {
        bx = g_gbox[grp * NMS_CAP + tid];
        ps = g_gpos[grp * NMS_CAP + tid];
        rkraw[tid] = ps;
    }
    __syncthreads();
    if (tid == 0) g_gcnt[grp] = 0u;
    int myrank = 0;
    if (tid < n)
        for (int j = 0; j < n; j++) myrank += (rkraw[j] < ps) ? 1 : 0;
    __syncthreads();
    if (tid < n) {
        sy1[myrank] = bx.x; sx1[myrank] = bx.y;
        sy2[myrank] = bx.z; sx2[myrank] = bx.w;
        sarea[myrank] = (bx.z - bx.x + 1.0f) * (bx.w - bx.y + 1.0f);
        spos[myrank] = ps;
    }
    __syncthreads();

    int nw = (n + 31) >> 5;

    // forward suppression masks; t = w*n + i (i fastest): lanes share w,
    // consecutive i -> conflict-free mask stores with MSTRIDE=33
    int total = nw * n;
    for (int t = tid; t < total; t += blockDim.x) {
        int w = t / n;
        int i = t - w * n;
        if (w < (i >> 5)) { mask[i * MSTRIDE + w] = 0u; continue; }
        float iy1 = sy1[i], ix1 = sx1[i], iy2 = sy2[i], ix2 = sx2[i];
        float ia = sarea[i];
        unsigned int mw = 0u;
        int jb = w << 5;
#pragma unroll 8
        for (int b = 0; b < 32; b++) {
            int j = jb + b;
            if (j > i && j < n) {
                float ih  = fminf(iy2, sy2[j]) - fmaxf(iy1, sy1[j]) + 1.0f;
                float iw2 = fminf(ix2, sx2[j]) - fmaxf(ix1, sx1[j]) + 1.0f;
                ih = fmaxf(ih, 0.0f); iw2 = fmaxf(iw2, 0.0f);
                float inter = ih * iw2;
                if (inter >= 0.5f * (ia + sarea[j] - inter)) mw |= (1u << b);
            }
        }
        mask[i * MSTRIDE + w] = mw;
    }
    __syncthreads();

    // greedy bit-reduce (warp 0), visiting only still-alive boxes via ffs
    if (tid < 32) {
        unsigned int remv = 0u;
        for (int c = 0; c < nw; c++) {
            unsigned int alive = ~__shfl_sync(0xFFFFFFFFu, remv, c);
            if (c == nw - 1 && (n & 31)) alive &= (1u << (n & 31)) - 1u;
            while (alive) {
                int b = __ffs(alive) - 1;
                int i = (c << 5) + b;
                unsigned int row = (tid < nw) ? mask[i * MSTRIDE + tid] : 0u;
                remv |= row;
                unsigned int rowc = __shfl_sync(0xFFFFFFFFu, row, c);
                alive &= ~rowc;
                alive &= ~(1u << b);
            }
        }
        s_remv[tid] = remv;
    }
    __syncthreads();

    for (int j = tid; j < n; j += blockDim.x)
        out[spos[j] * 6 + 5] = ((s_remv[j >> 5] >> (j & 31)) & 1u) ? 0.0f : 1.0f;
}

// ---------------- launch ----------------
extern "C" void kernel_launch(void* const* d_in, const int* in_sizes, int n_in,
                              void* d_out, int out_size) {
    const float* probs   = (const float*)d_in[0];
    const float* deltas  = (const float*)d_in[1];
    const float* anchors = (const float*)d_in[2];
    float* out = (float*)d_out;

    int n_prop    = in_sizes[0] / 3;
    int n_anchors = in_sizes[2] / 4;
    int n_groups  = n_prop / 4;          // 4 props (12 floats = 3 float4) per thread-step

    const int hist_smem = H16BINS * 4;                          // 65536 bytes
    const int nms_smem  = NMS_CAP * (5 * 4 + 4 + MSTRIDE * 4);  // 156672 bytes
    static int attr_set = 0;
    if (!attr_set) {
        cudaFuncSetAttribute(k_hist16, cudaFuncAttributeMaxDynamicSharedMemorySize, hist_smem);
        cudaFuncSetAttribute(k_nms, cudaFuncAttributeMaxDynamicSharedMemorySize, nms_smem);
        attr_set = 1;
    }

    int gb = (n_groups + 511) / 512;     // 1 group per thread

    k_hist16<<<gb, 512, hist_smem>>>(probs, n_groups);
    k_binit<<<1, 1024>>>();
    k_scatter<<<gb, 512>>>(probs, n_groups);
    k_rank<<<256, 512>>>(deltas, anchors, out, n_anchors);
    k_nms<<<NGROUPS, 1024, nms_smem>>>(out);
}

// round 14
// speedup vs baseline: 1.0162x; 1.0162x over previous
#include <cuda_runtime.h>
#include <math.h>

#define K_TOP    6000
#define CAND_CAP 16384
#define NMS_CAP  1024
#define H16BINS  16384     // 16-bit score-prefix bins: (u>>16)-0x8000
#define MSTRIDE  33        // padded mask row stride (no 32-way bank conflicts)
#define NGROUPS  16
#define NBLOCKS  148
#define NTHREADS 1024

// ---------------- scratch (device globals; no allocations) ----------------
__device__ unsigned int       g_hist16[H16BINS];
__device__ unsigned int       g_base[H16BINS];    // per-bin exact global rank base
__device__ unsigned int       g_cursor[H16BINS];  // per-bin scatter cursor
__device__ unsigned int       g_meta[8];          // [0]=t16 crossing bin
__device__ unsigned long long g_cand[CAND_CAP];   // bucketed candidates
__device__ float4             g_gbox[NGROUPS * NMS_CAP];
__device__ int                g_gpos[NGROUPS * NMS_CAP];
__device__ unsigned int       g_gcnt[NGROUPS];
__device__ unsigned int       g_barrier;          // monotonic ticket (never reset)

// order-preserving float<->uint transform
__device__ __forceinline__ unsigned int f2u(float f) {
    unsigned int b = __float_as_uint(f);
    return b ^ ((b & 0x80000000u) ? 0xFFFFFFFFu : 0x80000000u);
}
__device__ __forceinline__ float u2f(unsigned int u) {
    unsigned int b = (u & 0x80000000u) ? (u ^ 0x80000000u) : ~u;
    return __uint_as_float(b);
}
__device__ __forceinline__ int bin16(unsigned int u) {
    int b = (int)(u >> 16) - 0x8000;
    b = (b < 0) ? 0 : b;
    return (b > H16BINS - 1) ? H16BINS - 1 : b;
}

// grid-wide barrier: monotonic generation ticket; safe across graph replays.
// All NBLOCKS blocks are co-resident (1 block/SM by smem), so spinning is safe.
__device__ __forceinline__ void grid_sync() {
    __syncthreads();
    if (threadIdx.x == 0) {
        __threadfence();                                   // release
        unsigned int t = atomicAdd(&g_barrier, 1u);
        unsigned int target = (t / NBLOCKS + 1u) * NBLOCKS;
        while (true) {
            unsigned int v = *(volatile unsigned int*)&g_barrier;
            if ((int)(v - target) >= 0) break;             // wrap-safe
            __nanosleep(32);
        }
        __threadfence();                                   // acquire
    }
    __syncthreads();
}

__global__ __launch_bounds__(NTHREADS, 1)
void k_fused(const float* __restrict__ probs,
             const float* __restrict__ deltas,
             const float* __restrict__ anchors,
             float* __restrict__ out,
             int n_groups, int n_anchors) {
    extern __shared__ unsigned char dyn[];
    int tid  = threadIdx.x;
    int lane = tid & 31;

    // ============ phase 1: 16-bit-prefix histogram ============
    {
        unsigned int* sh = (unsigned int*)dyn;             // H16BINS
        for (int k = tid; k < H16BINS; k += NTHREADS) sh[k] = 0u;
        __syncthreads();

        const float4* __restrict__ p4 = (const float4*)probs;
        int stride = NBLOCKS * NTHREADS;
        for (int g = blockIdx.x * NTHREADS + tid; g < n_groups; g += stride) {
            float4 A = p4[g * 3 + 0], B = p4[g * 3 + 1], C = p4[g * 3 + 2];
            float s[8] = {A.y, A.z, B.x, B.y, B.w, C.x, C.z, C.w};
#pragma unroll
            for (int k = 0; k < 8; k++) {
                int bin = bin16(f2u(s[k]));
                unsigned int act = __activemask();
                unsigned int peers = __match_any_sync(act, bin);
                int leader = __ffs(peers) - 1;
                if (lane == leader)
                    atomicAdd(&sh[bin], (unsigned int)__popc(peers));
            }
        }
        __syncthreads();
        for (int k = tid; k < H16BINS; k += NTHREADS) {
            unsigned int v = sh[k];
            if (v) atomicAdd(&g_hist16[k], v);
        }
    }
    grid_sync();

    // ============ phase 2: bases + cursors + crossing bin (block 0) ============
    if (blockIdx.x == 0) {
        __shared__ unsigned int ssum[NTHREADS];
        const int bpt = H16BINS / NTHREADS;    // 16
        int base = tid * bpt;
        unsigned int h[H16BINS / NTHREADS];
        unsigned int cs = 0;
#pragma unroll
        for (int k = 0; k < bpt; k++) { h[k] = g_hist16[base + k]; cs += h[k]; }
        ssum[tid] = cs; __syncthreads();
        for (int off = 1; off < NTHREADS; off <<= 1) {     // inclusive suffix sum
            unsigned int v = (tid + off < NTHREADS) ? ssum[tid + off] : 0u;
            __syncthreads();
            ssum[tid] += v;
            __syncthreads();
        }
        unsigned int excl = (tid < NTHREADS - 1) ? ssum[tid + 1] : 0u;

        unsigned int run = excl;                           // suffix base per bin
#pragma unroll
        for (int k = bpt - 1; k >= 0; k--) {
            g_base[base + k] = run;
            g_cursor[base + k] = run;
            run += h[k];
        }
        if (ssum[tid] >= (unsigned)K_TOP && excl < (unsigned)K_TOP) {
            unsigned int r2 = excl;
            for (int k = bpt - 1; k >= 0; k--) {
                if (r2 + h[k] >= (unsigned)K_TOP) { g_meta[0] = (unsigned int)(base + k); break; }
                r2 += h[k];
            }
        }
    }
    grid_sync();

    // ============ phase 3: scatter candidates into bin segments ============
    {
        int t16 = (int)g_meta[0];
        const float4* __restrict__ p4 = (const float4*)probs;
        int stride = NBLOCKS * NTHREADS;
        for (int g = blockIdx.x * NTHREADS + tid; g < n_groups; g += stride) {
            float4 A = p4[g * 3 + 0], B = p4[g * 3 + 1], C = p4[g * 3 + 2];
            float s[8] = {A.y, A.z, B.x, B.y, B.w, C.x, C.z, C.w};
#pragma unroll
            for (int k = 0; k < 8; k++) {
                unsigned int u = f2u(s[k]);
                int bin = bin16(u);
                bool e = (bin >= t16);
                unsigned int act = __activemask();
                unsigned int ball_e = __ballot_sync(act, e);
                if (ball_e) {
                    unsigned int peers = __match_any_sync(act, bin) & ball_e;
                    if (e) {
                        int leader = __ffs(peers) - 1;
                        unsigned int basep = 0;
                        if (lane == leader)
                            basep = atomicAdd(&g_cursor[bin], (unsigned int)__popc(peers));
                        basep = __shfl_sync(ball_e, basep, leader);
                        unsigned int my = basep + __popc(peers & ((1u << lane) - 1u));
                        if (my < CAND_CAP) {
                            unsigned int flat =
                                (unsigned int)((g * 4 + (k >> 1)) * 2 + (k & 1));
                            g_cand[my] = ((unsigned long long)u << 32) |
                                         (unsigned long long)(0xFFFFFFFFu - flat);
                        }
                    }
                }
            }
        }
    }
    grid_sync();

    // ============ phase 4: bucketed exact rank + decode + group scatter ============
    {
        int t16 = (int)g_meta[0];
        int m = (int)min(g_base[t16] + g_hist16[t16], (unsigned int)CAND_CAP);
        int warp = blockIdx.x * (NTHREADS >> 5) + (tid >> 5);
        int nwarps = NBLOCKS * (NTHREADS >> 5);

        for (int item = warp; item < m; item += nwarps) {
            unsigned long long key = g_cand[item];
            int bin = bin16((unsigned int)(key >> 32));
            int seg0 = (int)g_base[bin];
            int segn = (int)g_hist16[bin];

            unsigned int cnt = 0u;
            for (int j = seg0 + lane; j < seg0 + segn; j += 32)
                cnt += (g_cand[j] > key) ? 1u : 0u;
#pragma unroll
            for (int off = 16; off > 0; off >>= 1)
                cnt += __shfl_down_sync(0xFFFFFFFFu, cnt, off);

            if (lane == 0) {
                int rk = seg0 + (int)cnt;
                if (rk < K_TOP) {
                    unsigned int u = (unsigned int)(key >> 32);
                    unsigned int flat = 0xFFFFFFFFu - (unsigned int)(key & 0xFFFFFFFFu);
                    int prop = (int)(flat >> 1);
                    int cls = (int)(flat & 1u) + 1;
                    float score = u2f(u);
                    int b = prop / n_anchors;
                    int ai = prop - b * n_anchors;

                    const float* a  = anchors + (size_t)ai * 4;
                    const float* dl = deltas + (size_t)prop * 4;
                    float d0 = dl[0] * 0.1f, d1 = dl[1] * 0.1f;
                    float d2 = dl[2] * 0.2f, d3 = dl[3] * 0.2f;

                    const float inv = 1.0f / 512.0f;
                    float ay1 = a[0] * inv, ax1 = a[1] * inv;
                    float ay2 = a[2] * inv, ax2 = a[3] * inv;
                    float h  = ay2 - ay1;
                    float w2 = ax2 - ax1;
                    float cy = ay1 + 0.5f * h + d0 * h;
                    float cx = ax1 + 0.5f * w2 + d1 * w2;
                    h  = h * expf(d2);
                    w2 = w2 * expf(d3);
                    float y1 = cy - 0.5f * h;
                    float x1 = cx - 0.5f * w2;
                    float y2 = y1 + h;
                    float x2 = x1 + w2;
                    y1 = fminf(fmaxf(y1 * 512.0f, 0.0f), 512.0f);
                    x1 = fminf(fmaxf(x1 * 512.0f, 0.0f), 512.0f);
                    y2 = fminf(fmaxf(y2 * 512.0f, 0.0f), 512.0f);
                    x2 = fminf(fmaxf(x2 * 512.0f, 0.0f), 512.0f);

                    out[rk * 6 + 0] = y1;
                    out[rk * 6 + 1] = x1;
                    out[rk * 6 + 2] = y2;
                    out[rk * 6 + 3] = x2;
                    out[rk * 6 + 4] = score;
                    out[rk * 6 + 5] = 1.0f;                 // keep (finalized by NMS)
                    out[K_TOP * 6 + rk] = (float)cls;       // class_ids
                    out[K_TOP * 7 + rk] = (float)b;         // batch ids

                    int grp = b * 2 + (int)(flat & 1u);
                    unsigned int slot = atomicAdd(&g_gcnt[grp], 1u);
                    if (slot < NMS_CAP) {
                        g_gbox[grp * NMS_CAP + slot] = make_float4(y1, x1, y2, x2);
                        g_gpos[grp * NMS_CAP + slot] = rk;
                    }
                }
            }
        }
    }
    grid_sync();

    // ============ phase 5: per-group NMS (blocks 0..15) + cleanup ============
    if (blockIdx.x >= NGROUPS) return;
    {
        float* sy1   = (float*)dyn;
        float* sx1   = sy1 + NMS_CAP;
        float* sy2   = sx1 + NMS_CAP;
        float* sx2   = sy2 + NMS_CAP;
        float* sarea = sx2 + NMS_CAP;
        int* spos    = (int*)(sarea + NMS_CAP);
        unsigned int* mask = (unsigned int*)(spos + NMS_CAP);  // [NMS_CAP][MSTRIDE]
        int* rkraw = (int*)mask;                               // pre-mask scratch

        __shared__ unsigned int s_remv[32];
        int grp = blockIdx.x;

        // cleanup for next replay: 16 blocks x 1024 threads = 16384 bins
        g_hist16[grp * 1024 + tid] = 0u;
        // (g_base/g_cursor/g_meta rewritten by phase 2 each replay)

        int n = min((int)g_gcnt[grp], NMS_CAP);

        // load raw (unordered) entries; sort by global rank via rank-by-count
        float4 bx = make_float4(0.f, 0.f, 0.f, 0.f);
        int ps = 0;
        if (tid < n) {
            bx = g_gbox[grp * NMS_CAP + tid];
            ps = g_gpos[grp * NMS_CAP + tid];
            rkraw[tid] = ps;
        }
        __syncthreads();
        if (tid == 0) g_gcnt[grp] = 0u;
        int myrank = 0;
        if (tid < n)
            for (int j = 0; j < n; j++) myrank += (rkraw[j] < ps) ? 1 : 0;
        __syncthreads();
        if (tid < n) {
            sy1[myrank] = bx.x; sx1[myrank] = bx.y;
            sy2[myrank] = bx.z; sx2[myrank] = bx.w;
            sarea[myrank] = (bx.z - bx.x + 1.0f) * (bx.w - bx.y + 1.0f);
            spos[myrank] = ps;
        }
        __syncthreads();

        int nw = (n + 31) >> 5;

        // forward suppression masks; t = w*n + i (i fastest)
        int total = nw * n;
        for (int t = tid; t < total; t += NTHREADS) {
            int w = t / n;
            int i = t - w * n;
            if (w < (i >> 5)) { mask[i * MSTRIDE + w] = 0u; continue; }
            float iy1 = sy1[i], ix1 = sx1[i], iy2 = sy2[i], ix2 = sx2[i];
            float ia = sarea[i];
            unsigned int mw = 0u;
            int jb = w << 5;
#pragma unroll 8
            for (int b = 0; b < 32; b++) {
                int j = jb + b;
                if (j > i && j < n) {
                    float ih  = fminf(iy2, sy2[j]) - fmaxf(iy1, sy1[j]) + 1.0f;
                    float iw2 = fminf(ix2, sx2[j]) - fmaxf(ix1, sx1[j]) + 1.0f;
                    ih = fmaxf(ih, 0.0f); iw2 = fmaxf(iw2, 0.0f);
                    float inter = ih * iw2;
                    if (inter >= 0.5f * (ia + sarea[j] - inter)) mw |= (1u << b);
                }
            }
            mask[i * MSTRIDE + w] = mw;
        }
        __syncthreads();

        // greedy bit-reduce (warp 0), visiting only still-alive boxes via ffs
        if (tid < 32) {
            unsigned int remv = 0u;
            for (int c = 0; c < nw; c++) {
                unsigned int alive = ~__shfl_sync(0xFFFFFFFFu, remv, c);
                if (c == nw - 1 && (n & 31)) alive &= (1u << (n & 31)) - 1u;
                while (alive) {
                    int b = __ffs(alive) - 1;
                    int i = (c << 5) + b;
                    unsigned int row = (tid < nw) ? mask[i * MSTRIDE + tid] : 0u;
                    remv |= row;
                    unsigned int rowc = __shfl_sync(0xFFFFFFFFu, row, c);
                    alive &= ~rowc;
                    alive &= ~(1u << b);
                }
            }
            s_remv[tid] = remv;
        }
        __syncthreads();

        for (int j = tid; j < n; j += NTHREADS)
            out[spos[j] * 6 + 5] = ((s_remv[j >> 5] >> (j & 31)) & 1u) ? 0.0f : 1.0f;
    }
}

// ---------------- launch ----------------
extern "C" void kernel_launch(void* const* d_in, const int* in_sizes, int n_in,
                              void* d_out, int out_size) {
    const float* probs   = (const float*)d_in[0];
    const float* deltas  = (const float*)d_in[1];
    const float* anchors = (const float*)d_in[2];
    float* out = (float*)d_out;

    int n_prop    = in_sizes[0] / 3;
    int n_anchors = in_sizes[2] / 4;
    int n_groups  = n_prop / 4;

    // dyn smem = max(phase1 64KB hist, phase5 ~153KB nms) = 156672 bytes
    const int smem = NMS_CAP * (5 * 4 + 4 + MSTRIDE * 4);
    static int attr_set = 0;
    if (!attr_set) {
        cudaFuncSetAttribute(k_fused, cudaFuncAttributeMaxDynamicSharedMemorySize, smem);
        attr_set = 1;
    }

    k_fused<<<NBLOCKS, NTHREADS, smem>>>(probs, deltas, anchors, out,
                                         n_groups, n_anchors);
}

// round 15
// speedup vs baseline: 1.4614x; 1.4382x over previous
#include <cuda_runtime.h>
#include <math.h>

#define K_TOP    6000
#define CAND_CAP 16384
#define NMS_CAP  1024
#define H16BINS  16384     // 16-bit score-prefix bins: (u>>16)-0x8000
#define MSTRIDE  33        // padded mask row stride (no 32-way bank conflicts)
#define NGROUPS  16
#define NBLOCKS  148
#define NTHREADS 1024

// ---------------- scratch (device globals; no allocations) ----------------
__device__ unsigned int       g_hist16[H16BINS];
__device__ unsigned int       g_off[H16BINS];     // per-bin scatter offset (zeroed)
__device__ unsigned long long g_cand[CAND_CAP];   // bucketed candidates
__device__ float4             g_gbox[NGROUPS * NMS_CAP];
__device__ int                g_gpos[NGROUPS * NMS_CAP];
__device__ unsigned int       g_gcnt[NGROUPS];
__device__ unsigned int       g_barrier;          // monotonic ticket (never reset)

// order-preserving float<->uint transform
__device__ __forceinline__ unsigned int f2u(float f) {
    unsigned int b = __float_as_uint(f);
    return b ^ ((b & 0x80000000u) ? 0xFFFFFFFFu : 0x80000000u);
}
__device__ __forceinline__ float u2f(unsigned int u) {
    unsigned int b = (u & 0x80000000u) ? (u ^ 0x80000000u) : ~u;
    return __uint_as_float(b);
}
__device__ __forceinline__ int bin16(unsigned int u) {
    int b = (int)(u >> 16) - 0x8000;
    b = (b < 0) ? 0 : b;
    return (b > H16BINS - 1) ? H16BINS - 1 : b;
}

// grid-wide barrier: monotonic generation ticket; safe across graph replays.
// All NBLOCKS blocks are co-resident (1 block/SM by smem), so spinning is safe.
__device__ __forceinline__ void grid_sync() {
    __syncthreads();
    if (threadIdx.x == 0) {
        __threadfence();                                   // release
        unsigned int t = atomicAdd(&g_barrier, 1u);
        unsigned int target = (t / NBLOCKS + 1u) * NBLOCKS;
        while (true) {
            unsigned int v = *(volatile unsigned int*)&g_barrier;
            if ((int)(v - target) >= 0) break;             // wrap-safe
            __nanosleep(32);
        }
        __threadfence();                                   // acquire
    }
    __syncthreads();
}

__global__ __launch_bounds__(NTHREADS, 1)
void k_fused(const float* __restrict__ probs,
             const float* __restrict__ deltas,
             const float* __restrict__ anchors,
             float* __restrict__ out,
             int n_groups, int n_anchors) {
    extern __shared__ unsigned char dyn[];
    __shared__ unsigned int ssum[NTHREADS];
    __shared__ int s_t16, s_m;
    int tid  = threadIdx.x;
    int lane = tid & 31;

    // ============ phase 1: 16-bit-prefix histogram ============
    {
        unsigned int* sh = (unsigned int*)dyn;             // H16BINS
        for (int k = tid; k < H16BINS; k += NTHREADS) sh[k] = 0u;
        __syncthreads();

        const float4* __restrict__ p4 = (const float4*)probs;
        int stride = NBLOCKS * NTHREADS;
        for (int g = blockIdx.x * NTHREADS + tid; g < n_groups; g += stride) {
            float4 A = p4[g * 3 + 0], B = p4[g * 3 + 1], C = p4[g * 3 + 2];
            float s[8] = {A.y, A.z, B.x, B.y, B.w, C.x, C.z, C.w};
#pragma unroll
            for (int k = 0; k < 8; k++) {
                int bin = bin16(f2u(s[k]));
                unsigned int act = __activemask();
                unsigned int peers = __match_any_sync(act, bin);
                int leader = __ffs(peers) - 1;
                if (lane == leader)
                    atomicAdd(&sh[bin], (unsigned int)__popc(peers));
            }
        }
        __syncthreads();
        for (int k = tid; k < H16BINS; k += NTHREADS) {
            unsigned int v = sh[k];
            if (v) atomicAdd(&g_hist16[k], v);
        }
    }
    grid_sync();

    // ======== phase 2: per-block base prologue (smem) + scatter ========
    unsigned int* sbase = (unsigned int*)dyn;              // H16BINS bases
    {
        const int bpt = H16BINS / NTHREADS;                // 16
        int base = tid * bpt;
        unsigned int h[H16BINS / NTHREADS];
        unsigned int cs = 0;
#pragma unroll
        for (int k = 0; k < bpt; k++) { h[k] = g_hist16[base + k]; cs += h[k]; }
        ssum[tid] = cs; __syncthreads();
        for (int off = 1; off < NTHREADS; off <<= 1) {     // inclusive suffix sum
            unsigned int v = (tid + off < NTHREADS) ? ssum[tid + off] : 0u;
            __syncthreads();
            ssum[tid] += v;
            __syncthreads();
        }
        unsigned int excl = (tid < NTHREADS - 1) ? ssum[tid + 1] : 0u;

        unsigned int run = excl;                           // suffix base per bin
#pragma unroll
        for (int k = bpt - 1; k >= 0; k--) {
            sbase[base + k] = run;
            run += h[k];
        }
        if (ssum[tid] >= (unsigned)K_TOP && excl < (unsigned)K_TOP) {   // crossing
            unsigned int r2 = excl;
            for (int k = bpt - 1; k >= 0; k--) {
                if (r2 + h[k] >= (unsigned)K_TOP) {
                    s_t16 = base + k;
                    s_m = (int)min(r2 + h[k], (unsigned int)CAND_CAP);
                    break;
                }
                r2 += h[k];
            }
        }
        __syncthreads();
    }
    {
        int t16 = s_t16;
        const float4* __restrict__ p4 = (const float4*)probs;
        int stride = NBLOCKS * NTHREADS;
        for (int g = blockIdx.x * NTHREADS + tid; g < n_groups; g += stride) {
            float4 A = p4[g * 3 + 0], B = p4[g * 3 + 1], C = p4[g * 3 + 2];
            float s[8] = {A.y, A.z, B.x, B.y, B.w, C.x, C.z, C.w};
#pragma unroll
            for (int k = 0; k < 8; k++) {
                unsigned int u = f2u(s[k]);
                int bin = bin16(u);
                bool e = (bin >= t16);
                unsigned int act = __activemask();
                unsigned int ball_e = __ballot_sync(act, e);
                if (ball_e) {
                    unsigned int peers = __match_any_sync(act, bin) & ball_e;
                    if (e) {
                        int leader = __ffs(peers) - 1;
                        unsigned int offp = 0;
                        if (lane == leader)
                            offp = atomicAdd(&g_off[bin], (unsigned int)__popc(peers));
                        offp = __shfl_sync(ball_e, offp, leader);
                        unsigned int my = sbase[bin] + offp +
                                          __popc(peers & ((1u << lane) - 1u));
                        if (my < CAND_CAP) {
                            unsigned int flat =
                                (unsigned int)((g * 4 + (k >> 1)) * 2 + (k & 1));
                            g_cand[my] = ((unsigned long long)u << 32) |
                                         (unsigned long long)(0xFFFFFFFFu - flat);
                        }
                    }
                }
            }
        }
    }
    grid_sync();

    // ============ phase 3: bucketed exact rank + decode + group scatter ============
    {
        int m = s_m;                                       // block-local, identical
        int warp = blockIdx.x * (NTHREADS >> 5) + (tid >> 5);
        int nwarps = NBLOCKS * (NTHREADS >> 5);

        for (int item = warp; item < m; item += nwarps) {
            unsigned long long key = g_cand[item];
            int bin = bin16((unsigned int)(key >> 32));
            int seg0 = (int)sbase[bin];
            int segn = (int)g_hist16[bin];

            unsigned int cnt = 0u;
            for (int j = seg0 + lane; j < seg0 + segn; j += 32)
                cnt += (g_cand[j] > key) ? 1u : 0u;
#pragma unroll
            for (int off = 16; off > 0; off >>= 1)
                cnt += __shfl_down_sync(0xFFFFFFFFu, cnt, off);

            if (lane == 0) {
                int rk = seg0 + (int)cnt;
                if (rk < K_TOP) {
                    unsigned int u = (unsigned int)(key >> 32);
                    unsigned int flat = 0xFFFFFFFFu - (unsigned int)(key & 0xFFFFFFFFu);
                    int prop = (int)(flat >> 1);
                    int cls = (int)(flat & 1u) + 1;
                    float score = u2f(u);
                    int b = prop / n_anchors;
                    int ai = prop - b * n_anchors;

                    const float* a  = anchors + (size_t)ai * 4;
                    const float* dl = deltas + (size_t)prop * 4;
                    float d0 = dl[0] * 0.1f, d1 = dl[1] * 0.1f;
                    float d2 = dl[2] * 0.2f, d3 = dl[3] * 0.2f;

                    const float inv = 1.0f / 512.0f;
                    float ay1 = a[0] * inv, ax1 = a[1] * inv;
                    float ay2 = a[2] * inv, ax2 = a[3] * inv;
                    float h  = ay2 - ay1;
                    float w2 = ax2 - ax1;
                    float cy = ay1 + 0.5f * h + d0 * h;
                    float cx = ax1 + 0.5f * w2 + d1 * w2;
                    h  = h * expf(d2);
                    w2 = w2 * expf(d3);
                    float y1 = cy - 0.5f * h;
                    float x1 = cx - 0.5f * w2;
                    float y2 = y1 + h;
                    float x2 = x1 + w2;
                    y1 = fminf(fmaxf(y1 * 512.0f, 0.0f), 512.0f);
                    x1 = fminf(fmaxf(x1 * 512.0f, 0.0f), 512.0f);
                    y2 = fminf(fmaxf(y2 * 512.0f, 0.0f), 512.0f);
                    x2 = fminf(fmaxf(x2 * 512.0f, 0.0f), 512.0f);

                    out[rk * 6 + 0] = y1;
                    out[rk * 6 + 1] = x1;
                    out[rk * 6 + 2] = y2;
                    out[rk * 6 + 3] = x2;
                    out[rk * 6 + 4] = score;
                    out[rk * 6 + 5] = 1.0f;                 // keep (finalized by NMS)
                    out[K_TOP * 6 + rk] = (float)cls;       // class_ids
                    out[K_TOP * 7 + rk] = (float)b;         // batch ids

                    int grp = b * 2 + (int)(flat & 1u);
                    unsigned int slot = atomicAdd(&g_gcnt[grp], 1u);
                    if (slot < NMS_CAP) {
                        g_gbox[grp * NMS_CAP + slot] = make_float4(y1, x1, y2, x2);
                        g_gpos[grp * NMS_CAP + slot] = rk;
                    }
                }
            }
        }
    }
    grid_sync();

    // ============ phase 4: per-group NMS (blocks 0..15) + cleanup ============
    if (blockIdx.x >= NGROUPS) return;
    {
        float* sy1   = (float*)dyn;
        float* sx1   = sy1 + NMS_CAP;
        float* sy2   = sx1 + NMS_CAP;
        float* sx2   = sy2 + NMS_CAP;
        float* sarea = sx2 + NMS_CAP;
        int* spos    = (int*)(sarea + NMS_CAP);
        unsigned int* mask = (unsigned int*)(spos + NMS_CAP);  // [NMS_CAP][MSTRIDE]
        int* rkraw = (int*)mask;                               // pre-mask scratch

        __shared__ unsigned int s_remv[32];
        int grp = blockIdx.x;

        // cleanup for next replay: 16 blocks x 1024 threads cover both arrays
        g_hist16[grp * 1024 + tid] = 0u;
        g_off[grp * 1024 + tid] = 0u;

        int n = min((int)g_gcnt[grp], NMS_CAP);

        // load raw (unordered) entries; sort by global rank via rank-by-count
        float4 bx = make_float4(0.f, 0.f, 0.f, 0.f);
        int ps = 0;
        if (tid < n) {
            bx = g_gbox[grp * NMS_CAP + tid];
            ps = g_gpos[grp * NMS_CAP + tid];
            rkraw[tid] = ps;
        }
        __syncthreads();
        if (tid == 0) g_gcnt[grp] = 0u;
        int myrank = 0;
        if (tid < n)
            for (int j = 0; j < n; j++) myrank += (rkraw[j] < ps) ? 1 : 0;
        __syncthreads();
        if (tid < n) {
            sy1[myrank] = bx.x; sx1[myrank] = bx.y;
            sy2[myrank] = bx.z; sx2[myrank] = bx.w;
            sarea[myrank] = (bx.z - bx.x + 1.0f) * (bx.w - bx.y + 1.0f);
            spos[myrank] = ps;
        }
        __syncthreads();

        int nw = (n + 31) >> 5;

        // forward suppression masks; t = w*n + i (i fastest)
        int total = nw * n;
        for (int t = tid; t < total; t += NTHREADS) {
            int w = t / n;
            int i = t - w * n;
            if (w < (i >> 5)) { mask[i * MSTRIDE + w] = 0u; continue; }
            float iy1 = sy1[i], ix1 = sx1[i], iy2 = sy2[i], ix2 = sx2[i];
            float ia = sarea[i];
            unsigned int mw = 0u;
            int jb = w << 5;
#pragma unroll 8
            for (int b = 0; b < 32; b++) {
                int j = jb + b;
                if (j > i && j < n) {
                    float ih  = fminf(iy2, sy2[j]) - fmaxf(iy1, sy1[j]) + 1.0f;
                    float iw2 = fminf(ix2, sx2[j]) - fmaxf(ix1, sx1[j]) + 1.0f;
                    ih = fmaxf(ih, 0.0f); iw2 = fmaxf(iw2, 0.0f);
                    float inter = ih * iw2;
                    if (inter >= 0.5f * (ia + sarea[j] - inter)) mw |= (1u << b);
                }
            }
            mask[i * MSTRIDE + w] = mw;
        }
        __syncthreads();

        // greedy bit-reduce (warp 0): linear sweep, unconditional row prefetch
        if (tid < 32) {
            unsigned int remv = 0u;
            unsigned int row = (tid < nw && n > 0) ? mask[tid] : 0u;
            for (int i = 0; i < n; i++) {
                unsigned int nrow = (i + 1 < n && tid < nw)
                                    ? mask[(i + 1) * MSTRIDE + tid] : 0u;
                unsigned int wv = __shfl_sync(0xFFFFFFFFu, remv, i >> 5);
                if (!((wv >> (i & 31)) & 1u)) remv |= row;
                row = nrow;
            }
            s_remv[tid] = remv;
        }
        __syncthreads();

        for (int j = tid; j < n; j += NTHREADS)
            out[spos[j] * 6 + 5] = ((s_remv[j >> 5] >> (j & 31)) & 1u) ? 0.0f : 1.0f;
    }
}

// ---------------- launch ----------------
extern "C" void kernel_launch(void* const* d_in, const int* in_sizes, int n_in,
                              void* d_out, int out_size) {
    const float* probs   = (const float*)d_in[0];
    const float* deltas  = (const float*)d_in[1];
    const float* anchors = (const float*)d_in[2];
    float* out = (float*)d_out;

    int n_prop    = in_sizes[0] / 3;
    int n_anchors = in_sizes[2] / 4;
    int n_groups  = n_prop / 4;

    // dyn smem = max(64KB hist/bases, ~153KB nms) = 156672 bytes
    const int smem = NMS_CAP * (5 * 4 + 4 + MSTRIDE * 4);
    static int attr_set = 0;
    if (!attr_set) {
        cudaFuncSetAttribute(k_fused, cudaFuncAttributeMaxDynamicSharedMemorySize, smem);
        attr_set = 1;
    }

    k_fused<<<NBLOCKS, NTHREADS, smem>>>(probs, deltas, anchors, out,
                                         n_groups, n_anchors);
}

// round 16
// speedup vs baseline: 1.6548x; 1.1323x over previous
#include <cuda_runtime.h>
#include <math.h>

#define K_TOP    6000
#define CAND_CAP 16384
#define NMS_CAP  1024
#define H16BINS  16384     // 16-bit score-prefix bins: (u>>16)-0x8000
#define MSTRIDE  33        // padded mask row stride (no 32-way bank conflicts)
#define NGROUPS  16
#define NBLOCKS  148
#define NTHREADS 1024

// ---------------- scratch (device globals; no allocations) ----------------
__device__ unsigned int       g_hist16[H16BINS];
__device__ unsigned int       g_off[H16BINS];     // per-bin scatter offset (zeroed)
__device__ unsigned long long g_cand[CAND_CAP];   // bucketed candidates
__device__ float4             g_gbox[NGROUPS * NMS_CAP];
__device__ int                g_gpos[NGROUPS * NMS_CAP];
__device__ unsigned int       g_gcnt[NGROUPS];
__device__ unsigned int       g_barrier;          // monotonic ticket (never reset)

// order-preserving float<->uint transform
__device__ __forceinline__ unsigned int f2u(float f) {
    unsigned int b = __float_as_uint(f);
    return b ^ ((b & 0x80000000u) ? 0xFFFFFFFFu : 0x80000000u);
}
__device__ __forceinline__ float u2f(unsigned int u) {
    unsigned int b = (u & 0x80000000u) ? (u ^ 0x80000000u) : ~u;
    return __uint_as_float(b);
}
// scores are softmax outputs in [0,1]: u>>16 ∈ [0x8000, 0xBF80] ⊂ [0, H16BINS)
__device__ __forceinline__ int bin16(unsigned int u) {
    return (int)(u >> 16) - 0x8000;
}

// grid-wide barrier: monotonic generation ticket; safe across graph replays.
// All NBLOCKS blocks are co-resident (1 block/SM by smem), so spinning is safe.
__device__ __forceinline__ void grid_sync() {
    __syncthreads();
    if (threadIdx.x == 0) {
        __threadfence();                                   // release
        unsigned int t = atomicAdd(&g_barrier, 1u);
        unsigned int target = (t / NBLOCKS + 1u) * NBLOCKS;
        while (true) {
            unsigned int v = *(volatile unsigned int*)&g_barrier;
            if ((int)(v - target) >= 0) break;             // wrap-safe
            __nanosleep(32);
        }
        __threadfence();                                   // acquire
    }
    __syncthreads();
}

__global__ __launch_bounds__(NTHREADS, 1)
void k_fused(const float* __restrict__ probs,
             const float* __restrict__ deltas,
             const float* __restrict__ anchors,
             float* __restrict__ out,
             int n_groups, int n_anchors) {
    extern __shared__ unsigned char dyn[];
    __shared__ unsigned int ssum[NTHREADS];
    __shared__ int s_t16, s_m;
    int tid  = threadIdx.x;
    int lane = tid & 31;

    // ============ phase 1: 16-bit-prefix histogram (plain smem atomics) ============
    {
        unsigned int* sh = (unsigned int*)dyn;             // H16BINS
        for (int k = tid; k < H16BINS; k += NTHREADS) sh[k] = 0u;
        __syncthreads();

        const float4* __restrict__ p4 = (const float4*)probs;
        int stride = NBLOCKS * NTHREADS;
        for (int g = blockIdx.x * NTHREADS + tid; g < n_groups; g += stride) {
            float4 A = p4[g * 3 + 0], B = p4[g * 3 + 1], C = p4[g * 3 + 2];
            float s[8] = {A.y, A.z, B.x, B.y, B.w, C.x, C.z, C.w};
#pragma unroll
            for (int k = 0; k < 8; k++)
                atomicAdd(&sh[bin16(f2u(s[k]))], 1u);
        }
        __syncthreads();
        for (int k = tid; k < H16BINS; k += NTHREADS) {
            unsigned int v = sh[k];
            if (v) atomicAdd(&g_hist16[k], v);
        }
    }
    grid_sync();

    // ======== phase 2: per-block base prologue (smem) + scatter ========
    unsigned int* sbase = (unsigned int*)dyn;              // H16BINS bases
    {
        const int bpt = H16BINS / NTHREADS;                // 16
        int base = tid * bpt;
        unsigned int h[H16BINS / NTHREADS];
        unsigned int cs = 0;
#pragma unroll
        for (int k = 0; k < bpt; k++) { h[k] = g_hist16[base + k]; cs += h[k]; }
        ssum[tid] = cs; __syncthreads();
        for (int off = 1; off < NTHREADS; off <<= 1) {     // inclusive suffix sum
            unsigned int v = (tid + off < NTHREADS) ? ssum[tid + off] : 0u;
            __syncthreads();
            ssum[tid] += v;
            __syncthreads();
        }
        unsigned int excl = (tid < NTHREADS - 1) ? ssum[tid + 1] : 0u;

        unsigned int run = excl;                           // suffix base per bin
#pragma unroll
        for (int k = bpt - 1; k >= 0; k--) {
            sbase[base + k] = run;
            run += h[k];
        }
        if (ssum[tid] >= (unsigned)K_TOP && excl < (unsigned)K_TOP) {   // crossing
            unsigned int r2 = excl;
            for (int k = bpt - 1; k >= 0; k--) {
                if (r2 + h[k] >= (unsigned)K_TOP) {
                    s_t16 = base + k;
                    s_m = (int)min(r2 + h[k], (unsigned int)CAND_CAP);
                    break;
                }
                r2 += h[k];
            }
        }
        __syncthreads();
    }
    {
        // fast-path predicate: bin>=t16  <=>  u >= (t16+0x8000)<<16
        unsigned int thr_u = ((unsigned int)s_t16 + 0x8000u) << 16;
        const float4* __restrict__ p4 = (const float4*)probs;
        int stride = NBLOCKS * NTHREADS;
        for (int g = blockIdx.x * NTHREADS + tid; g < n_groups; g += stride) {
            float4 A = p4[g * 3 + 0], B = p4[g * 3 + 1], C = p4[g * 3 + 2];
            float s[8] = {A.y, A.z, B.x, B.y, B.w, C.x, C.z, C.w};
#pragma unroll
            for (int k = 0; k < 8; k++) {
                unsigned int u = f2u(s[k]);
                bool e = (u >= thr_u);
                unsigned int act = __activemask();
                unsigned int ball_e = __ballot_sync(act, e);
                if (ball_e) {                              // rare: ~6600 of 2M
                    int bin = bin16(u);
                    unsigned int peers = __match_any_sync(act, bin) & ball_e;
                    if (e) {
                        int leader = __ffs(peers) - 1;
                        unsigned int offp = 0;
                        if (lane == leader)
                            offp = atomicAdd(&g_off[bin], (unsigned int)__popc(peers));
                        offp = __shfl_sync(ball_e, offp, leader);
                        unsigned int my = sbase[bin] + offp +
                                          __popc(peers & ((1u << lane) - 1u));
                        if (my < CAND_CAP) {
                            unsigned int flat =
                                (unsigned int)((g * 4 + (k >> 1)) * 2 + (k & 1));
                            g_cand[my] = ((unsigned long long)u << 32) |
                                         (unsigned long long)(0xFFFFFFFFu - flat);
                        }
                    }
                }
            }
        }
    }
    grid_sync();

    // ============ phase 3: bucketed exact rank + decode + group scatter ============
    {
        int m = s_m;                                       // block-local, identical
        int warp = blockIdx.x * (NTHREADS >> 5) + (tid >> 5);
        int nwarps = NBLOCKS * (NTHREADS >> 5);

        for (int item = warp; item < m; item += nwarps) {
            unsigned long long key = g_cand[item];
            int bin = bin16((unsigned int)(key >> 32));
            int seg0 = (int)sbase[bin];
            int segn = (int)g_hist16[bin];

            unsigned int cnt = 0u;
            for (int j = seg0 + lane; j < seg0 + segn; j += 32)
                cnt += (g_cand[j] > key) ? 1u : 0u;
#pragma unroll
            for (int off = 16; off > 0; off >>= 1)
                cnt += __shfl_down_sync(0xFFFFFFFFu, cnt, off);

            if (lane == 0) {
                int rk = seg0 + (int)cnt;
                if (rk < K_TOP) {
                    unsigned int u = (unsigned int)(key >> 32);
                    unsigned int flat = 0xFFFFFFFFu - (unsigned int)(key & 0xFFFFFFFFu);
                    int prop = (int)(flat >> 1);
                    int cls = (int)(flat & 1u) + 1;
                    float score = u2f(u);
                    int b = prop / n_anchors;
                    int ai = prop - b * n_anchors;

                    const float* a  = anchors + (size_t)ai * 4;
                    const float* dl = deltas + (size_t)prop * 4;
                    float d0 = dl[0] * 0.1f, d1 = dl[1] * 0.1f;
                    float d2 = dl[2] * 0.2f, d3 = dl[3] * 0.2f;

                    const float inv = 1.0f / 512.0f;
                    float ay1 = a[0] * inv, ax1 = a[1] * inv;
                    float ay2 = a[2] * inv, ax2 = a[3] * inv;
                    float h  = ay2 - ay1;
                    float w2 = ax2 - ax1;
                    float cy = ay1 + 0.5f * h + d0 * h;
                    float cx = ax1 + 0.5f * w2 + d1 * w2;
                    h  = h * expf(d2);
                    w2 = w2 * expf(d3);
                    float y1 = cy - 0.5f * h;
                    float x1 = cx - 0.5f * w2;
                    float y2 = y1 + h;
                    float x2 = x1 + w2;
                    y1 = fminf(fmaxf(y1 * 512.0f, 0.0f), 512.0f);
                    x1 = fminf(fmaxf(x1 * 512.0f, 0.0f), 512.0f);
                    y2 = fminf(fmaxf(y2 * 512.0f, 0.0f), 512.0f);
                    x2 = fminf(fmaxf(x2 * 512.0f, 0.0f), 512.0f);

                    out[rk * 6 + 0] = y1;
                    out[rk * 6 + 1] = x1;
                    out[rk * 6 + 2] = y2;
                    out[rk * 6 + 3] = x2;
                    out[rk * 6 + 4] = score;
                    out[rk * 6 + 5] = 1.0f;                 // keep (finalized by NMS)
                    out[K_TOP * 6 + rk] = (float)cls;       // class_ids
                    out[K_TOP * 7 + rk] = (float)b;         // batch ids

                    int grp = b * 2 + (int)(flat & 1u);
                    unsigned int slot = atomicAdd(&g_gcnt[grp], 1u);
                    if (slot < NMS_CAP) {
                        g_gbox[grp * NMS_CAP + slot] = make_float4(y1, x1, y2, x2);
                        g_gpos[grp * NMS_CAP + slot] = rk;
                    }
                }
            }
        }
    }
    grid_sync();

    // ============ phase 4: per-group NMS (blocks 0..15) + cleanup ============
    if (blockIdx.x >= NGROUPS) return;
    {
        float* sy1   = (float*)dyn;
        float* sx1   = sy1 + NMS_CAP;
        float* sy2   = sx1 + NMS_CAP;
        float* sx2   = sy2 + NMS_CAP;
        float* sarea = sx2 + NMS_CAP;
        int* spos    = (int*)(sarea + NMS_CAP);
        unsigned int* mask = (unsigned int*)(spos + NMS_CAP);  // [NMS_CAP][MSTRIDE]
        int* rkraw = (int*)mask;                               // pre-mask scratch

        __shared__ unsigned int s_remv[32];
        int grp = blockIdx.x;

        // cleanup for next replay: 16 blocks x 1024 threads cover both arrays
        g_hist16[grp * 1024 + tid] = 0u;
        g_off[grp * 1024 + tid] = 0u;

        int n = min((int)g_gcnt[grp], NMS_CAP);

        // load raw (unordered) entries; sort by global rank via rank-by-count
        float4 bx = make_float4(0.f, 0.f, 0.f, 0.f);
        int ps = 0;
        if (tid < n) {
            bx = g_gbox[grp * NMS_CAP + tid];
            ps = g_gpos[grp * NMS_CAP + tid];
            rkraw[tid] = ps;
        }
        __syncthreads();
        if (tid == 0) g_gcnt[grp] = 0u;
        int myrank = 0;
        if (tid < n)
            for (int j = 0; j < n; j++) myrank += (rkraw[j] < ps) ? 1 : 0;
        __syncthreads();
        if (tid < n) {
            sy1[myrank] = bx.x; sx1[myrank] = bx.y;
            sy2[myrank] = bx.z; sx2[myrank] = bx.w;
            sarea[myrank] = (bx.z - bx.x + 1.0f) * (bx.w - bx.y + 1.0f);
            spos[myrank] = ps;
        }
        __syncthreads();

        int nw = (n + 31) >> 5;

        // forward suppression masks; t = w*n + i (i fastest)
        int total = nw * n;
        for (int t = tid; t < total; t += NTHREADS) {
            int w = t / n;
            int i = t - w * n;
            if (w < (i >> 5)) { mask[i * MSTRIDE + w] = 0u; continue; }
            float iy1 = sy1[i], ix1 = sx1[i], iy2 = sy2[i], ix2 = sx2[i];
            float ia = sarea[i];
            unsigned int mw = 0u;
            int jb = w << 5;
#pragma unroll 8
            for (int b = 0; b < 32; b++) {
                int j = jb + b;
                if (j > i && j < n) {
                    float ih  = fminf(iy2, sy2[j]) - fmaxf(iy1, sy1[j]) + 1.0f;
                    float iw2 = fminf(ix2, sx2[j]) - fmaxf(ix1, sx1[j]) + 1.0f;
                    ih = fmaxf(ih, 0.0f); iw2 = fmaxf(iw2, 0.0f);
                    float inter = ih * iw2;
                    if (inter >= 0.5f * (ia + sarea[j] - inter)) mw |= (1u << b);
                }
            }
            mask[i * MSTRIDE + w] = mw;
        }
        __syncthreads();

        // greedy bit-reduce (warp 0): linear sweep, unconditional row prefetch
        if (tid < 32) {
            unsigned int remv = 0u;
            unsigned int row = (tid < nw && n > 0) ? mask[tid] : 0u;
            for (int i = 0; i < n; i++) {
                unsigned int nrow = (i + 1 < n && tid < nw)
                                    ? mask[(i + 1) * MSTRIDE + tid] : 0u;
                unsigned int wv = __shfl_sync(0xFFFFFFFFu, remv, i >> 5);
                if (!((wv >> (i & 31)) & 1u)) remv |= row;
                row = nrow;
            }
            s_remv[tid] = remv;
        }
        __syncthreads();

        for (int j = tid; j < n; j += NTHREADS)
            out[spos[j] * 6 + 5] = ((s_remv[j >> 5] >> (j & 31)) & 1u) ? 0.0f : 1.0f;
    }
}

// ---------------- launch ----------------
extern "C" void kernel_launch(void* const* d_in, const int* in_sizes, int n_in,
                              void* d_out, int out_size) {
    const float* probs   = (const float*)d_in[0];
    const float* deltas  = (const float*)d_in[1];
    const float* anchors = (const float*)d_in[2];
    float* out = (float*)d_out;

    int n_prop    = in_sizes[0] / 3;
    int n_anchors = in_sizes[2] / 4;
    int n_groups  = n_prop / 4;

    // dyn smem = max(64KB hist/bases, ~153KB nms) = 156672 bytes
    const int smem = NMS_CAP * (5 * 4 + 4 + MSTRIDE * 4);
    static int attr_set = 0;
    if (!attr_set) {
        cudaFuncSetAttribute(k_fused, cudaFuncAttributeMaxDynamicSharedMemorySize, smem);
        attr_set = 1;
    }

    k_fused<<<NBLOCKS, NTHREADS, smem>>>(probs, deltas, anchors, out,
                                         n_groups, n_anchors);
}